// round 5
// baseline (speedup 1.0000x reference)
#include <cuda_runtime.h>
#include <math.h>

#define N_BODY 512
#define NV 6890
#define NVP 6912          // padded vertex count (div by 128)
#define NJ 24
#define NP 207

typedef unsigned long long ull;

__device__ __constant__ int d_parents[NJ] =
    {0, 0, 0, 0, 1, 2, 3, 4, 5, 6, 7, 8, 9, 9, 9, 12, 13, 14, 16, 17, 18, 19, 20, 21};

// ---------------- scratch (device globals; no allocations) ----------------
__device__ float g_JT[NJ * 3];
__device__ float g_JS[NJ * 30];
__device__ float g_jregT[NJ * NV];            // [j][v]
__device__ float g_lrot2[NP * 2 * N_BODY];    // duplicated pairs: [p][2n], [p][2n+1] same value
__device__ float g_GT[NJ * 12 * N_BODY];      // [j*12+e][n]
__device__ float g_transT[3 * N_BODY];        // [c][n]
__device__ float g_vs[3 * N_BODY * NVP];      // v_shaped [c][n][v] padded
__device__ float g_pdT[NP * 3 * NVP];         // posedirs [p][c][v] padded

// ---------------- f32x2 helpers ----------------
__device__ __forceinline__ ull pk2(float a, float b) {
    ull r; asm("mov.b64 %0, {%1, %2};" : "=l"(r) : "f"(a), "f"(b)); return r;
}
__device__ __forceinline__ void upk2(float& a, float& b, ull v) {
    asm("mov.b64 {%0, %1}, %2;" : "=f"(a), "=f"(b) : "l"(v));
}
__device__ __forceinline__ ull fma2_(ull a, ull b, ull c) {
    ull d; asm("fma.rn.f32x2 %0, %1, %2, %3;" : "=l"(d) : "l"(a), "l"(b), "l"(c)); return d;
}

// ---------------- kernel 1: reduce J_regressor against template/shapedirs ----------------
__global__ void k_pre(const float* __restrict__ Jreg,
                      const float* __restrict__ vt,
                      const float* __restrict__ sd) {
    int j = blockIdx.x;
    int tid = threadIdx.x;
    float acc[33];
#pragma unroll
    for (int i = 0; i < 33; i++) acc[i] = 0.f;
    for (int v = tid; v < NV; v += 256) {
        float r = Jreg[j * NV + v];
#pragma unroll
        for (int c = 0; c < 3; c++) acc[c] += r * vt[v * 3 + c];
#pragma unroll
        for (int i = 0; i < 30; i++) acc[3 + i] += r * sd[v * 30 + i];
    }
#pragma unroll
    for (int i = 0; i < 33; i++) {
#pragma unroll
        for (int off = 16; off > 0; off >>= 1)
            acc[i] += __shfl_down_sync(0xffffffff, acc[i], off);
    }
    __shared__ float red[8][34];
    int wid = tid >> 5, lane = tid & 31;
    if (lane == 0) {
#pragma unroll
        for (int i = 0; i < 33; i++) red[wid][i] = acc[i];
    }
    __syncthreads();
    if (tid < 33) {
        float s = 0.f;
#pragma unroll
        for (int wq = 0; wq < 8; wq++) s += red[wq][tid];
        if (tid < 3) g_JT[j * 3 + tid] = s;
        else         g_JS[j * 30 + (tid - 3)] = s;
    }
}

// ---------------- kernel 2: transpose joint_regressor ----------------
__global__ void k_jregT(const float* __restrict__ jreg) {
    int v = blockIdx.x * blockDim.x + threadIdx.x;
    if (v < NV) {
#pragma unroll
        for (int j = 0; j < NJ; j++) g_jregT[j * NV + v] = jreg[v * NJ + j];
    }
}

// ---------------- kernel: transpose posedirs -> [p][c][v] (padded, zero-filled) ----------------
__global__ void k_pdT(const float* __restrict__ pd) {
    __shared__ float sm[16 * 625];
    int tid = threadIdx.x;
    int vbase = blockIdx.x * 16;
    for (int i = tid; i < 16 * 621; i += 256) {
        int vl = i / 621, col = i % 621;
        int v = vbase + vl;
        sm[vl * 625 + col] = (v < NV) ? pd[(size_t)v * 621 + col] : 0.f;
    }
    __syncthreads();
    for (int i = tid; i < 621 * 16; i += 256) {
        int pc = i >> 4, vl = i & 15;   // pc = c*207 + p
        int c = pc / 207, p = pc % 207;
        g_pdT[(p * 3 + c) * NVP + vbase + vl] = sm[vl * 625 + pc];
    }
}

// ---------------- kernel: shape blend -> g_vs [c][n][v] ----------------
__global__ void k_shape(const float* __restrict__ betas,
                        const float* __restrict__ vt,
                        const float* __restrict__ sd) {
    __shared__ float bet[80];
    int tid = threadIdx.x;
    int nb = blockIdx.x * 8;
    int v = blockIdx.y * 256 + tid;
    if (tid < 80) bet[tid] = betas[nb * 10 + tid];
    __syncthreads();
    if (v >= NVP) return;
    float vt3[3] = {0.f, 0.f, 0.f};
    float s[30];
    if (v < NV) {
#pragma unroll
        for (int c = 0; c < 3; c++) vt3[c] = vt[v * 3 + c];
#pragma unroll
        for (int i = 0; i < 30; i++) s[i] = sd[v * 30 + i];
    } else {
#pragma unroll
        for (int i = 0; i < 30; i++) s[i] = 0.f;
    }
#pragma unroll
    for (int nl = 0; nl < 8; nl++) {
#pragma unroll
        for (int c = 0; c < 3; c++) {
            float a = vt3[c];
#pragma unroll
            for (int k = 0; k < 10; k++) a += bet[nl * 10 + k] * s[c * 10 + k];
            g_vs[(size_t)c * N_BODY * NVP + (size_t)(nb + nl) * NVP + v] = a;
        }
    }
}

// ---------------- kernel: per-body rodrigues + FK ----------------
__global__ void k_body(const float* __restrict__ betas,
                       const float* __restrict__ thetas,
                       const float* __restrict__ trans) {
    int n = blockIdx.x;
    int lane = threadIdx.x;
    __shared__ float sR[NJ][9];
    __shared__ float sJ[NJ][3];
    __shared__ float sT[NJ][3];
    __shared__ float sG[NJ][12];

    if (lane < NJ) {
        int j = lane;
        float b[10];
#pragma unroll
        for (int k = 0; k < 10; k++) b[k] = betas[n * 10 + k];
#pragma unroll
        for (int c = 0; c < 3; c++) {
            float a = g_JT[j * 3 + c];
#pragma unroll
            for (int k = 0; k < 10; k++) a += g_JS[j * 30 + c * 10 + k] * b[k];
            sJ[j][c] = a;
        }
        float rx = thetas[n * 72 + j * 3 + 0];
        float ry = thetas[n * 72 + j * 3 + 1];
        float rz = thetas[n * 72 + j * 3 + 2];
        float th = sqrtf(rx * rx + ry * ry + rz * rz) + 1e-8f;
        float inv = 1.0f / th;
        float x = rx * inv, y = ry * inv, z = rz * inv;
        float ct = cosf(th), st = sinf(th), oc = 1.0f - ct;
        sR[j][0] = ct + oc * x * x;      sR[j][1] = oc * x * y - st * z;  sR[j][2] = oc * x * z + st * y;
        sR[j][3] = oc * y * x + st * z;  sR[j][4] = ct + oc * y * y;      sR[j][5] = oc * y * z - st * x;
        sR[j][6] = oc * z * x - st * y;  sR[j][7] = oc * z * y + st * x;  sR[j][8] = ct + oc * z * z;
    }
    __syncwarp();
    if (lane < NJ) {
        int j = lane;
        if (j == 0) {
#pragma unroll
            for (int c = 0; c < 3; c++) sT[0][c] = sJ[0][c];
        } else {
            int p = d_parents[j];
#pragma unroll
            for (int c = 0; c < 3; c++) sT[j][c] = sJ[j][c] - sJ[p][c];
        }
    }
    __syncwarp();
    if (lane == 0) {
#pragma unroll
        for (int r = 0; r < 3; r++) {
            sG[0][r * 4 + 0] = sR[0][r * 3 + 0];
            sG[0][r * 4 + 1] = sR[0][r * 3 + 1];
            sG[0][r * 4 + 2] = sR[0][r * 3 + 2];
            sG[0][r * 4 + 3] = sT[0][r];
        }
        for (int j = 1; j < NJ; j++) {
            int p = d_parents[j];
            float Rn[9], tn[3];
#pragma unroll
            for (int r = 0; r < 3; r++) {
#pragma unroll
                for (int c = 0; c < 3; c++) {
                    Rn[r * 3 + c] = sG[p][r * 4 + 0] * sR[j][0 * 3 + c]
                                  + sG[p][r * 4 + 1] * sR[j][1 * 3 + c]
                                  + sG[p][r * 4 + 2] * sR[j][2 * 3 + c];
                }
                tn[r] = sG[p][r * 4 + 3]
                      + sG[p][r * 4 + 0] * sT[j][0]
                      + sG[p][r * 4 + 1] * sT[j][1]
                      + sG[p][r * 4 + 2] * sT[j][2];
            }
#pragma unroll
            for (int r = 0; r < 3; r++) {
                sG[j][r * 4 + 0] = Rn[r * 3 + 0];
                sG[j][r * 4 + 1] = Rn[r * 3 + 1];
                sG[j][r * 4 + 2] = Rn[r * 3 + 2];
                sG[j][r * 4 + 3] = tn[r];
            }
        }
    }
    __syncwarp();
    if (lane < NJ) {
        int j = lane;
        float t0 = sG[j][3]  - (sG[j][0] * sJ[j][0] + sG[j][1] * sJ[j][1] + sG[j][2]  * sJ[j][2]);
        float t1 = sG[j][7]  - (sG[j][4] * sJ[j][0] + sG[j][5] * sJ[j][1] + sG[j][6]  * sJ[j][2]);
        float t2 = sG[j][11] - (sG[j][8] * sJ[j][0] + sG[j][9] * sJ[j][1] + sG[j][10] * sJ[j][2]);
        sG[j][3] = t0; sG[j][7] = t1; sG[j][11] = t2;
    }
    __syncwarp();
    for (int idx = lane; idx < NJ * 12; idx += 32)
        g_GT[idx * N_BODY + n] = sG[idx / 12][idx % 12];
    for (int idx = lane; idx < NP; idx += 32) {
        int j = idx / 9 + 1;
        int e = idx % 9;
        float v = sR[j][e];
        if (e == 0 || e == 4 || e == 8) v -= 1.0f;
        g_lrot2[idx * 2 * N_BODY + 2 * n]     = v;
        g_lrot2[idx * 2 * N_BODY + 2 * n + 1] = v;
    }
    if (lane < 3) g_transT[lane * N_BODY + n] = trans[n * 3 + lane];
}

// ---------------- kernel: fused pose blend + LBS (f32x2, 8n x 4v tile) ----------------
#define TN 32
#define TV 128
#define PCH 23
#define NCH 9
#define PDS 388   // pd chunk row stride (floats), 16B-aligned

// smem layout (floats):
//   lrot2_s: [23][64]             at 0      (1472)
//   pd_s:    [23][3][128] (PDS)   at 1472   (8924)   -> end 10396
//   (sG overlay [288][32]=9216 over [0,10396))
//   w_s:     [24][4][32]          at 10396  (3072)   -> 13468
//   sOut:    [8][388]             at 13468  (3104)   -> 16572
#define OFF_PD   1472
#define OFF_W    10396
#define OFF_SOUT 13468
#define SM_FLOATS 16572

__global__ void __launch_bounds__(128, 3) k_main(const float* __restrict__ w,
                                                 float* __restrict__ out) {
    extern __shared__ float sm[];
    float* lrot2_s = sm;
    float* pd_s    = sm + OFF_PD;
    float* w_s     = sm + OFF_W;
    float* sOut    = sm + OFF_SOUT;

    int tid = threadIdx.x;
    int vg = tid & 31;
    int bg = tid >> 5;
    int vbase = blockIdx.x * TV;
    int nbase = blockIdx.y * TN;
    int v0 = vbase + vg * 4;
    int n0 = nbase + bg * 8;

    // ---- load weights, vi-interleaved: w_s[j*128 + vi*32 + vg] ----
    for (int i = tid; i < TV * 24; i += 128) {
        int vl = i / 24, j = i % 24;
        int v = vbase + vl;
        w_s[j * 128 + (vl & 3) * 32 + (vl >> 2)] = (v < NV) ? w[v * 24 + j] : 0.f;
    }

    // ---- acc init from v_shaped scratch (coalesced float4) ----
    ull acc[8][2][3];
#pragma unroll
    for (int b = 0; b < 8; b++) {
#pragma unroll
        for (int c = 0; c < 3; c++) {
            float4 q = *(const float4*)(g_vs + (size_t)c * N_BODY * NVP +
                                        (size_t)(n0 + b) * NVP + v0);
            acc[b][0][c] = pk2(q.x, q.y);
            acc[b][1][c] = pk2(q.z, q.w);
        }
    }

    // ---- pose blend over 9 chunks of 23 p ----
    for (int ch = 0; ch < NCH; ch++) {
        int pbase = ch * PCH;
        __syncthreads();
        for (int i = tid; i < PCH * 64; i += 128) {
            int pl = i >> 6, col = i & 63;
            lrot2_s[i] = g_lrot2[(pbase + pl) * 2 * N_BODY + 2 * nbase + col];
        }
        for (int i = tid; i < PCH * 3 * 32; i += 128) {
            int pl = i / 96, r = i % 96;
            int c = r >> 5, q = r & 31;
            *(float4*)(pd_s + pl * PDS + c * 128 + q * 4) =
                *(const float4*)(g_pdT + (size_t)((pbase + pl) * 3 + c) * NVP + vbase + q * 4);
        }
        __syncthreads();
#pragma unroll 1
        for (int pl = 0; pl < PCH; pl++) {
            const float* lrow = lrot2_s + pl * 64;
            ulonglong2 P0 = *(const ulonglong2*)(pd_s + pl * PDS + 0 * 128 + vg * 4);
            ulonglong2 P1 = *(const ulonglong2*)(pd_s + pl * PDS + 1 * 128 + vg * 4);
            ulonglong2 P2 = *(const ulonglong2*)(pd_s + pl * PDS + 2 * 128 + vg * 4);
#pragma unroll
            for (int b = 0; b < 8; b++) {
                ull l2 = *(const ull*)(lrow + 2 * (bg * 8 + b));
                acc[b][0][0] = fma2_(l2, P0.x, acc[b][0][0]);
                acc[b][1][0] = fma2_(l2, P0.y, acc[b][1][0]);
                acc[b][0][1] = fma2_(l2, P1.x, acc[b][0][1]);
                acc[b][1][1] = fma2_(l2, P1.y, acc[b][1][1]);
                acc[b][0][2] = fma2_(l2, P2.x, acc[b][0][2]);
                acc[b][1][2] = fma2_(l2, P2.y, acc[b][1][2]);
            }
        }
    }

    // ---- stage G' slice into smem (overlay lrot2+pd region) ----
    __syncthreads();
    float* sG = sm;   // [288][32]
    for (int i = tid; i < NJ * 12 * TN; i += 128)
        sG[i] = g_GT[(i >> 5) * N_BODY + nbase + (i & 31)];
    __syncthreads();

    int f2lim = NV - vbase;
    if (f2lim > TV) f2lim = TV;
    f2lim = f2lim * 3 / 2;           // float2 count in valid row span

    // ---- skinning per body-pair group ----
#pragma unroll 1
    for (int np = 0; np < 4; np++) {
        int bl = bg * 8 + 2 * np;
        int nn = nbase + bl;

        // repack: pose acc (packed over vert pairs) -> B (packed over body pair)
        ull B[4][3];
#pragma unroll
        for (int vp = 0; vp < 2; vp++) {
#pragma unroll
            for (int c = 0; c < 3; c++) {
                float a0, a1, b0, b1;
                upk2(a0, a1, acc[2 * np][vp][c]);
                upk2(b0, b1, acc[2 * np + 1][vp][c]);
                B[2 * vp][c]     = pk2(a0, b0);
                B[2 * vp + 1][c] = pk2(a1, b1);
            }
        }
        ull o[4][3];
#pragma unroll
        for (int c = 0; c < 3; c++) {
            ull t2 = *(const ull*)(g_transT + c * N_BODY + nn);
#pragma unroll
            for (int v = 0; v < 4; v++) o[v][c] = t2;
        }
#pragma unroll 1
        for (int j = 0; j < NJ; j++) {
            ull g2[12];
#pragma unroll
            for (int e = 0; e < 12; e++)
                g2[e] = *(const ull*)(sG + (j * 12 + e) * TN + bl);
#pragma unroll
            for (int v = 0; v < 4; v++) {
                float wv = w_s[j * 128 + v * 32 + vg];
                ull w2 = pk2(wv, wv);
                ull tx = fma2_(g2[0], B[v][0], fma2_(g2[1], B[v][1], fma2_(g2[2],  B[v][2], g2[3])));
                ull ty = fma2_(g2[4], B[v][0], fma2_(g2[5], B[v][1], fma2_(g2[6],  B[v][2], g2[7])));
                ull tz = fma2_(g2[8], B[v][0], fma2_(g2[9], B[v][1], fma2_(g2[10], B[v][2], g2[11])));
                o[v][0] = fma2_(w2, tx, o[v][0]);
                o[v][1] = fma2_(w2, ty, o[v][1]);
                o[v][2] = fma2_(w2, tz, o[v][2]);
            }
        }

        // stage this np-group's 8 bodies x 128 verts x 3 through smem
        __syncthreads();   // prior copy (or sG stage) done
#pragma unroll
        for (int v = 0; v < 4; v++) {
#pragma unroll
            for (int c = 0; c < 3; c++) {
                float x0, x1;
                upk2(x0, x1, o[v][c]);
                int col = (vg * 4 + v) * 3 + c;
                sOut[(bg * 2) * PDS + col]     = x0;
                sOut[(bg * 2 + 1) * PDS + col] = x1;
            }
        }
        __syncthreads();
        for (int i = tid; i < 8 * 192; i += 128) {
            int nl2 = i / 192, q = i % 192;
            if (q < f2lim) {
                int n = nbase + (nl2 >> 1) * 8 + 2 * np + (nl2 & 1);
                *(float2*)(out + (size_t)n * (NV * 3) + (size_t)vbase * 3 + 2 * q) =
                    *(const float2*)(sOut + nl2 * PDS + 2 * q);
            }
        }
    }
}

// ---------------- kernel: joint regression (warp-per-body, 8 bodies/block) ----------------
__global__ void __launch_bounds__(256) k_joints(const float* __restrict__ res,
                                                float* __restrict__ jout) {
    int wid = threadIdx.x >> 5, lane = threadIdx.x & 31;
    int n = blockIdx.x * 8 + wid;
    float acc[72];
#pragma unroll
    for (int i = 0; i < 72; i++) acc[i] = 0.f;
    for (int v = lane; v < NV; v += 32) {
        size_t o = ((size_t)n * NV + v) * 3;
        float r0 = res[o + 0], r1 = res[o + 1], r2 = res[o + 2];
#pragma unroll
        for (int j = 0; j < NJ; j++) {
            float jr = g_jregT[j * NV + v];
            acc[j * 3 + 0] += jr * r0;
            acc[j * 3 + 1] += jr * r1;
            acc[j * 3 + 2] += jr * r2;
        }
    }
#pragma unroll
    for (int i = 0; i < 72; i++) {
#pragma unroll
        for (int off = 16; off > 0; off >>= 1)
            acc[i] += __shfl_down_sync(0xffffffff, acc[i], off);
    }
    if (lane == 0) {
#pragma unroll
        for (int i = 0; i < 72; i++) jout[n * 72 + i] = acc[i];
    }
}

// ---------------- launch ----------------
extern "C" void kernel_launch(void* const* d_in, const int* in_sizes, int n_in,
                              void* d_out, int out_size) {
    const float* betas  = (const float*)d_in[0];
    const float* thetas = (const float*)d_in[1];
    const float* trans  = (const float*)d_in[2];
    const float* vt     = (const float*)d_in[3];
    const float* sd     = (const float*)d_in[4];
    const float* pd     = (const float*)d_in[5];
    const float* Jreg   = (const float*)d_in[6];
    const float* jreg   = (const float*)d_in[7];
    const float* w      = (const float*)d_in[8];
    float* out  = (float*)d_out;
    float* jout = out + (size_t)N_BODY * NV * 3;

    k_pre<<<NJ, 256>>>(Jreg, vt, sd);
    k_jregT<<<(NV + 255) / 256, 256>>>(jreg);
    k_pdT<<<(NVP + 15) / 16, 256>>>(pd);
    k_shape<<<dim3(N_BODY / 8, NVP / 256), 256>>>(betas, vt, sd);
    k_body<<<N_BODY, 32>>>(betas, thetas, trans);

    const int SMEM = SM_FLOATS * (int)sizeof(float);
    cudaFuncSetAttribute(k_main, cudaFuncAttributeMaxDynamicSharedMemorySize, SMEM);
    dim3 grid(NVP / TV, N_BODY / TN);
    k_main<<<grid, 128, SMEM>>>(w, out);

    k_joints<<<N_BODY / 8, 256>>>(out, jout);
}

// round 7
// speedup vs baseline: 2.7425x; 2.7425x over previous
#include <cuda_runtime.h>
#include <cuda_bf16.h>
#include <math.h>

#define N_BODY 512
#define NV 6890
#define NVP 6912
#define NJ 24
#define NP 207
#define GM 512
#define GN 20736          // 3 * NVP
#define GK 256            // 217 padded to 256
#define BM 128
#define BN 128
#define BK 64

typedef unsigned long long ull;

__device__ __constant__ int d_parents[NJ] =
    {0, 0, 0, 0, 1, 2, 3, 4, 5, 6, 7, 8, 9, 9, 9, 12, 13, 14, 16, 17, 18, 19, 20, 21};

// ---------------- scratch (device globals; no allocations) ----------------
__device__ float g_JT[NJ * 3];
__device__ float g_JS[NJ * 30];
__device__ float g_jregT[NJ * NV];
__device__ __align__(16) float g_GT[NJ * 12 * N_BODY];      // [j*12+e][n]
__device__ __align__(16) float g_transT[3 * N_BODY];        // [c][n]
__device__ __align__(16) __nv_bfloat16 g_A[GM * GK];        // [n][k]  k-major
__device__ __align__(16) __nv_bfloat16 g_B[GN * GK];        // [col=(c*NVP+v)][k] k-major
__device__ __align__(16) float g_C[(size_t)GM * GN];        // pose+shape delta [n][c*NVP+v]

// ---------------- f32x2 helpers ----------------
__device__ __forceinline__ ull pk2(float a, float b) {
    ull r; asm("mov.b64 %0, {%1, %2};" : "=l"(r) : "f"(a), "f"(b)); return r;
}
__device__ __forceinline__ void upk2(float& a, float& b, ull v) {
    asm("mov.b64 {%0, %1}, %2;" : "=f"(a), "=f"(b) : "l"(v));
}
__device__ __forceinline__ ull fma2_(ull a, ull b, ull c) {
    ull d; asm("fma.rn.f32x2 %0, %1, %2, %3;" : "=l"(d) : "l"(a), "l"(b), "l"(c)); return d;
}
__device__ __forceinline__ ull add2_(ull a, ull b) {
    ull d; asm("add.rn.f32x2 %0, %1, %2;" : "=l"(d) : "l"(a), "l"(b)); return d;
}

// ---------------- tensor-core helpers ----------------
__device__ __forceinline__ void cp16(unsigned dst, const void* src) {
    asm volatile("cp.async.cg.shared.global [%0], [%1], 16;" :: "r"(dst), "l"(src));
}
__device__ __forceinline__ void ldm4(unsigned* r, unsigned addr) {
    asm volatile("ldmatrix.sync.aligned.m8n8.x4.shared.b16 {%0,%1,%2,%3}, [%4];"
        : "=r"(r[0]), "=r"(r[1]), "=r"(r[2]), "=r"(r[3]) : "r"(addr));
}
__device__ __forceinline__ void mma16816(float* d, const unsigned* a, const unsigned* b) {
    asm volatile("mma.sync.aligned.m16n8k16.row.col.f32.bf16.bf16.f32 "
        "{%0,%1,%2,%3}, {%4,%5,%6,%7}, {%8,%9}, {%0,%1,%2,%3};"
        : "+f"(d[0]), "+f"(d[1]), "+f"(d[2]), "+f"(d[3])
        : "r"(a[0]), "r"(a[1]), "r"(a[2]), "r"(a[3]), "r"(b[0]), "r"(b[1]));
}
__device__ __forceinline__ int swz(int off) { return off ^ ((off >> 3) & 0x70); }

// ---------------- kernel: reduce J_regressor against template/shapedirs ----------------
__global__ void k_pre(const float* __restrict__ Jreg,
                      const float* __restrict__ vt,
                      const float* __restrict__ sd) {
    int j = blockIdx.x;
    int tid = threadIdx.x;
    float acc[33];
#pragma unroll
    for (int i = 0; i < 33; i++) acc[i] = 0.f;
    for (int v = tid; v < NV; v += 256) {
        float r = Jreg[j * NV + v];
#pragma unroll
        for (int c = 0; c < 3; c++) acc[c] += r * vt[v * 3 + c];
#pragma unroll
        for (int i = 0; i < 30; i++) acc[3 + i] += r * sd[v * 30 + i];
    }
#pragma unroll
    for (int i = 0; i < 33; i++) {
#pragma unroll
        for (int off = 16; off > 0; off >>= 1)
            acc[i] += __shfl_down_sync(0xffffffff, acc[i], off);
    }
    __shared__ float red[8][34];
    int wid = tid >> 5, lane = tid & 31;
    if (lane == 0) {
#pragma unroll
        for (int i = 0; i < 33; i++) red[wid][i] = acc[i];
    }
    __syncthreads();
    if (tid < 33) {
        float s = 0.f;
#pragma unroll
        for (int wq = 0; wq < 8; wq++) s += red[wq][tid];
        if (tid < 3) g_JT[j * 3 + tid] = s;
        else         g_JS[j * 30 + (tid - 3)] = s;
    }
}

// ---------------- kernel: transpose joint_regressor ----------------
__global__ void k_jregT(const float* __restrict__ jreg) {
    int v = blockIdx.x * blockDim.x + threadIdx.x;
    if (v < NV) {
#pragma unroll
        for (int j = 0; j < NJ; j++) g_jregT[j * NV + v] = jreg[v * NJ + j];
    }
}

// ---------------- kernel: build bf16 B matrix [col=(c*NVP+v)][k] ----------------
// k 0-9: shapedirs, 10-216: posedirs, 217-255: zero. v >= NV rows zero.
__global__ void __launch_bounds__(256) k_Bbuild(const float* __restrict__ sd,
                                                const float* __restrict__ pd) {
    int wid = threadIdx.x >> 5, lane = threadIdx.x & 31;
    int row = blockIdx.x * 8 + wid;            // 0 .. 20735
    int c = row / NVP, v = row % NVP;
#pragma unroll
    for (int t = 0; t < 8; t++) {
        int k = t * 32 + lane;
        float val = 0.f;
        if (v < NV) {
            if (k < 10)       val = sd[v * 30 + c * 10 + k];
            else if (k < 217) val = pd[(size_t)v * 621 + c * 207 + (k - 10)];
        }
        g_B[(size_t)row * GK + k] = __float2bfloat16(val);
    }
}

// ---------------- kernel: per-body rodrigues + FK + A row ----------------
__global__ void k_body(const float* __restrict__ betas,
                       const float* __restrict__ thetas,
                       const float* __restrict__ trans) {
    int n = blockIdx.x;
    int lane = threadIdx.x;
    __shared__ float sR[NJ][9];
    __shared__ float sJ[NJ][3];
    __shared__ float sT[NJ][3];
    __shared__ float sG[NJ][12];

    if (lane < NJ) {
        int j = lane;
        float b[10];
#pragma unroll
        for (int k = 0; k < 10; k++) b[k] = betas[n * 10 + k];
#pragma unroll
        for (int c = 0; c < 3; c++) {
            float a = g_JT[j * 3 + c];
#pragma unroll
            for (int k = 0; k < 10; k++) a += g_JS[j * 30 + c * 10 + k] * b[k];
            sJ[j][c] = a;
        }
        float rx = thetas[n * 72 + j * 3 + 0];
        float ry = thetas[n * 72 + j * 3 + 1];
        float rz = thetas[n * 72 + j * 3 + 2];
        float th = sqrtf(rx * rx + ry * ry + rz * rz) + 1e-8f;
        float inv = 1.0f / th;
        float x = rx * inv, y = ry * inv, z = rz * inv;
        float ct = cosf(th), st = sinf(th), oc = 1.0f - ct;
        sR[j][0] = ct + oc * x * x;      sR[j][1] = oc * x * y - st * z;  sR[j][2] = oc * x * z + st * y;
        sR[j][3] = oc * y * x + st * z;  sR[j][4] = ct + oc * y * y;      sR[j][5] = oc * y * z - st * x;
        sR[j][6] = oc * z * x - st * y;  sR[j][7] = oc * z * y + st * x;  sR[j][8] = ct + oc * z * z;
    }
    __syncwarp();
    if (lane < NJ) {
        int j = lane;
        if (j == 0) {
#pragma unroll
            for (int c = 0; c < 3; c++) sT[0][c] = sJ[0][c];
        } else {
            int p = d_parents[j];
#pragma unroll
            for (int c = 0; c < 3; c++) sT[j][c] = sJ[j][c] - sJ[p][c];
        }
    }
    __syncwarp();
    if (lane == 0) {
#pragma unroll
        for (int r = 0; r < 3; r++) {
            sG[0][r * 4 + 0] = sR[0][r * 3 + 0];
            sG[0][r * 4 + 1] = sR[0][r * 3 + 1];
            sG[0][r * 4 + 2] = sR[0][r * 3 + 2];
            sG[0][r * 4 + 3] = sT[0][r];
        }
        for (int j = 1; j < NJ; j++) {
            int p = d_parents[j];
            float Rn[9], tn[3];
#pragma unroll
            for (int r = 0; r < 3; r++) {
#pragma unroll
                for (int c = 0; c < 3; c++) {
                    Rn[r * 3 + c] = sG[p][r * 4 + 0] * sR[j][0 * 3 + c]
                                  + sG[p][r * 4 + 1] * sR[j][1 * 3 + c]
                                  + sG[p][r * 4 + 2] * sR[j][2 * 3 + c];
                }
                tn[r] = sG[p][r * 4 + 3]
                      + sG[p][r * 4 + 0] * sT[j][0]
                      + sG[p][r * 4 + 1] * sT[j][1]
                      + sG[p][r * 4 + 2] * sT[j][2];
            }
#pragma unroll
            for (int r = 0; r < 3; r++) {
                sG[j][r * 4 + 0] = Rn[r * 3 + 0];
                sG[j][r * 4 + 1] = Rn[r * 3 + 1];
                sG[j][r * 4 + 2] = Rn[r * 3 + 2];
                sG[j][r * 4 + 3] = tn[r];
            }
        }
    }
    __syncwarp();
    if (lane < NJ) {
        int j = lane;
        float t0 = sG[j][3]  - (sG[j][0] * sJ[j][0] + sG[j][1] * sJ[j][1] + sG[j][2]  * sJ[j][2]);
        float t1 = sG[j][7]  - (sG[j][4] * sJ[j][0] + sG[j][5] * sJ[j][1] + sG[j][6]  * sJ[j][2]);
        float t2 = sG[j][11] - (sG[j][8] * sJ[j][0] + sG[j][9] * sJ[j][1] + sG[j][10] * sJ[j][2]);
        sG[j][3] = t0; sG[j][7] = t1; sG[j][11] = t2;
    }
    __syncwarp();
    for (int idx = lane; idx < NJ * 12; idx += 32)
        g_GT[idx * N_BODY + n] = sG[idx / 12][idx % 12];
    // A row: [betas(10) | lrotmin(207) | zeros]
#pragma unroll
    for (int t = 0; t < 8; t++) {
        int k = t * 32 + lane;
        float val = 0.f;
        if (k < 10) val = betas[n * 10 + k];
        else if (k < 217) {
            int idx = k - 10;
            int j = idx / 9 + 1, e = idx % 9;
            val = sR[j][e];
            if (e == 0 || e == 4 || e == 8) val -= 1.0f;
        }
        g_A[n * GK + k] = __float2bfloat16(val);
    }
    if (lane < 3) g_transT[lane * N_BODY + n] = trans[n * 3 + lane];
}

// ---------------- kernel: bf16 GEMM  C[512 x 20736] = A @ B^T (both k-major) ----------------
// 256 threads, warp grid 2(M) x 4(N), warp tile 64x32, BK=64, double-buffered cp.async
__global__ void __launch_bounds__(256) k_gemm(float* __restrict__ C) {
    extern __shared__ char smc[];
    unsigned smem = (unsigned)__cvta_generic_to_shared(smc);
    int tid = threadIdx.x, lane = tid & 31, wid = tid >> 5;
    int warp_m = (wid >> 2) * 64, warp_n = (wid & 3) * 32;
    int nb = blockIdx.x * BN, mb = blockIdx.y * BM;

    float acc[4][4][4] = {};

    // stage buffers: A at stage*16384, B at 32768 + stage*16384
#define LOAD_STAGE(stage, kb)                                                      \
    {                                                                              \
        unsigned sa = smem + (stage) * 16384;                                      \
        unsigned sb = smem + 32768 + (stage) * 16384;                              \
        _Pragma("unroll")                                                          \
        for (int t = 0; t < 4; t++) {                                              \
            int cc = tid + t * 256;                                                \
            int row = cc >> 3, u = cc & 7;                                         \
            int off = swz(row * 128 + u * 16);                                     \
            cp16(sa + off, (const char*)g_A + (size_t)(mb + row) * 512 + (kb) * 128 + u * 16); \
            cp16(sb + off, (const char*)g_B + (size_t)(nb + row) * 512 + (kb) * 128 + u * 16); \
        }                                                                          \
        asm volatile("cp.async.commit_group;");                                    \
    }

    LOAD_STAGE(0, 0);
#pragma unroll
    for (int kb = 0; kb < 4; kb++) {
        if (kb < 3) LOAD_STAGE((kb + 1) & 1, kb + 1);
        if (kb < 3) asm volatile("cp.async.wait_group 1;");
        else        asm volatile("cp.async.wait_group 0;");
        __syncthreads();
        unsigned sa = smem + (kb & 1) * 16384;
        unsigned sb = smem + 32768 + (kb & 1) * 16384;
#pragma unroll
        for (int s = 0; s < 4; s++) {
            unsigned af[4][4], bf[4][2], r[4];
#pragma unroll
            for (int mf = 0; mf < 4; mf++) {
                int row = warp_m + mf * 16 + (lane & 7) + ((lane >> 3) & 1) * 8;
                ldm4(af[mf], sa + swz(row * 128 + s * 32 + ((lane >> 4) & 1) * 16));
            }
#pragma unroll
            for (int nh = 0; nh < 2; nh++) {
                int row = warp_n + nh * 16 + (lane & 7) + ((lane >> 4) & 1) * 8;
                ldm4(r, sb + swz(row * 128 + s * 32 + ((lane >> 3) & 1) * 16));
                bf[nh * 2][0] = r[0]; bf[nh * 2][1] = r[1];
                bf[nh * 2 + 1][0] = r[2]; bf[nh * 2 + 1][1] = r[3];
            }
#pragma unroll
            for (int mf = 0; mf < 4; mf++)
#pragma unroll
                for (int nf = 0; nf < 4; nf++)
                    mma16816(acc[mf][nf], af[mf], bf[nf]);
        }
        __syncthreads();
    }

    // epilogue: direct float2 stores
#pragma unroll
    for (int mf = 0; mf < 4; mf++) {
#pragma unroll
        for (int nf = 0; nf < 4; nf++) {
            int r0 = mb + warp_m + mf * 16 + (lane >> 2);
            int col = nb + warp_n + nf * 8 + (lane & 3) * 2;
            *(float2*)&C[(size_t)r0 * GN + col] = make_float2(acc[mf][nf][0], acc[mf][nf][1]);
            *(float2*)&C[(size_t)(r0 + 8) * GN + col] = make_float2(acc[mf][nf][2], acc[mf][nf][3]);
        }
    }
#undef LOAD_STAGE
}

// ---------------- kernel: v_posed = C + vt, then LBS (f32x2 over body pairs) ----------------
// block 128 thr: 32 bodies x 128 verts; thread = body-octet (bg) x vert-quad (vg)
// smem: sG [288][32] at 0 (9216 f), w dup [24][256] at 9216 (6144 f), sOut [8][388] at 15360 (3104 f)
#define SKF 18464
__global__ void __launch_bounds__(128) k_skin(const float* __restrict__ vt,
                                              const float* __restrict__ w,
                                              float* __restrict__ out) {
    extern __shared__ float sm[];
    float* sG  = sm;
    float* w_s = sm + 9216;
    float* sOut = sm + 15360;

    int tid = threadIdx.x;
    int vbase = blockIdx.x * 128;
    int nbase = blockIdx.y * 32;

    for (int i = tid; i < NJ * 12 * 32; i += 128)
        sG[i] = g_GT[(i >> 5) * N_BODY + nbase + (i & 31)];
    for (int i = tid; i < 24 * 128; i += 128) {
        int j = i >> 7, vl = i & 127;
        int v = vbase + vl;
        float wv = (v < NV) ? w[v * 24 + j] : 0.f;
        w_s[j * 256 + 2 * vl] = wv;
        w_s[j * 256 + 2 * vl + 1] = wv;
    }
    __syncthreads();

    int vg = tid & 31, bg = tid >> 5;
    int v0 = vbase + vg * 4;
    int n0 = nbase + bg * 8;

    // vt for my 4 verts, packed (same value both lanes of body pair)
    float vtv[12];
    if (v0 + 4 <= NV) {
        float4 a = *(const float4*)(vt + v0 * 3);
        float4 b = *(const float4*)(vt + v0 * 3 + 4);
        float4 c = *(const float4*)(vt + v0 * 3 + 8);
        vtv[0]=a.x; vtv[1]=a.y; vtv[2]=a.z; vtv[3]=a.w;
        vtv[4]=b.x; vtv[5]=b.y; vtv[6]=b.z; vtv[7]=b.w;
        vtv[8]=c.x; vtv[9]=c.y; vtv[10]=c.z; vtv[11]=c.w;
    } else {
#pragma unroll
        for (int vv = 0; vv < 4; vv++)
#pragma unroll
            for (int c = 0; c < 3; c++)
                vtv[vv * 3 + c] = (v0 + vv < NV) ? vt[(v0 + vv) * 3 + c] : 0.f;
    }
    ull vtb[4][3];
#pragma unroll
    for (int vv = 0; vv < 4; vv++)
#pragma unroll
        for (int c = 0; c < 3; c++)
            vtb[vv][c] = pk2(vtv[vv * 3 + c], vtv[vv * 3 + c]);

    int f2lim = NV - vbase;
    if (f2lim > 128) f2lim = 128;
    f2lim = f2lim * 3 / 2;

#pragma unroll 1
    for (int np = 0; np < 4; np++) {
        int b0 = n0 + 2 * np;
        int bl = bg * 8 + 2 * np;

        // v_posed packed over body pair
        ull B[4][3];
#pragma unroll
        for (int c = 0; c < 3; c++) {
            const float* base0 = g_C + (size_t)b0 * GN + c * NVP + v0;
            float4 qa = *(const float4*)base0;
            float4 qb = *(const float4*)(base0 + GN);
            B[0][c] = add2_(pk2(qa.x, qb.x), vtb[0][c]);
            B[1][c] = add2_(pk2(qa.y, qb.y), vtb[1][c]);
            B[2][c] = add2_(pk2(qa.z, qb.z), vtb[2][c]);
            B[3][c] = add2_(pk2(qa.w, qb.w), vtb[3][c]);
        }

        ull o[4][3];
#pragma unroll
        for (int c = 0; c < 3; c++) {
            ull t2 = *(const ull*)(g_transT + c * N_BODY + b0);
#pragma unroll
            for (int vv = 0; vv < 4; vv++) o[vv][c] = t2;
        }
#pragma unroll 1
        for (int j = 0; j < NJ; j++) {
            ull g2[12];
#pragma unroll
            for (int e = 0; e < 12; e++)
                g2[e] = *(const ull*)(sG + (j * 12 + e) * 32 + bl);
#pragma unroll
            for (int vv = 0; vv < 4; vv++) {
                ull w2 = *(const ull*)(w_s + j * 256 + (vg * 4 + vv) * 2);
                ull tx = fma2_(g2[0], B[vv][0], fma2_(g2[1], B[vv][1], fma2_(g2[2],  B[vv][2], g2[3])));
                ull ty = fma2_(g2[4], B[vv][0], fma2_(g2[5], B[vv][1], fma2_(g2[6],  B[vv][2], g2[7])));
                ull tz = fma2_(g2[8], B[vv][0], fma2_(g2[9], B[vv][1], fma2_(g2[10], B[vv][2], g2[11])));
                o[vv][0] = fma2_(w2, tx, o[vv][0]);
                o[vv][1] = fma2_(w2, ty, o[vv][1]);
                o[vv][2] = fma2_(w2, tz, o[vv][2]);
            }
        }

        // stage through smem, store coalesced
#pragma unroll
        for (int vv = 0; vv < 4; vv++) {
#pragma unroll
            for (int c = 0; c < 3; c++) {
                float x0, x1;
                upk2(x0, x1, o[vv][c]);
                int col = (vg * 4 + vv) * 3 + c;
                sOut[(bg * 2) * 388 + col]     = x0;
                sOut[(bg * 2 + 1) * 388 + col] = x1;
            }
        }
        __syncthreads();
        for (int i = tid; i < 8 * 192; i += 128) {
            int nl2 = i / 192, q = i % 192;
            if (q < f2lim) {
                int n = nbase + (nl2 >> 1) * 8 + 2 * np + (nl2 & 1);
                *(float2*)(out + (size_t)n * (NV * 3) + (size_t)vbase * 3 + 2 * q) =
                    *(const float2*)(sOut + nl2 * 388 + 2 * q);
            }
        }
        __syncthreads();
    }
}

// ---------------- kernel: joint regression ----------------
__global__ void __launch_bounds__(256) k_joints(const float* __restrict__ res,
                                                float* __restrict__ jout) {
    int n = blockIdx.x;
    int tid = threadIdx.x;
    float acc[72];
#pragma unroll
    for (int i = 0; i < 72; i++) acc[i] = 0.f;
    for (int v = tid; v < NV; v += 256) {
        size_t o = ((size_t)n * NV + v) * 3;
        float r0 = res[o + 0], r1 = res[o + 1], r2 = res[o + 2];
#pragma unroll
        for (int j = 0; j < NJ; j++) {
            float jr = g_jregT[j * NV + v];
            acc[j * 3 + 0] += jr * r0;
            acc[j * 3 + 1] += jr * r1;
            acc[j * 3 + 2] += jr * r2;
        }
    }
#pragma unroll
    for (int i = 0; i < 72; i++) {
#pragma unroll
        for (int off = 16; off > 0; off >>= 1)
            acc[i] += __shfl_down_sync(0xffffffff, acc[i], off);
    }
    __shared__ float red[8][72];
    int wid = tid >> 5, lanei = tid & 31;
    if (lanei == 0) {
#pragma unroll
        for (int i = 0; i < 72; i++) red[wid][i] = acc[i];
    }
    __syncthreads();
    if (tid < 72) {
        float s = 0.f;
#pragma unroll
        for (int wq = 0; wq < 8; wq++) s += red[wq][tid];
        jout[n * 72 + tid] = s;
    }
}

// ---------------- launch ----------------
extern "C" void kernel_launch(void* const* d_in, const int* in_sizes, int n_in,
                              void* d_out, int out_size) {
    const float* betas  = (const float*)d_in[0];
    const float* thetas = (const float*)d_in[1];
    const float* trans  = (const float*)d_in[2];
    const float* vt     = (const float*)d_in[3];
    const float* sd     = (const float*)d_in[4];
    const float* pd     = (const float*)d_in[5];
    const float* Jreg   = (const float*)d_in[6];
    const float* jreg   = (const float*)d_in[7];
    const float* w      = (const float*)d_in[8];
    float* out  = (float*)d_out;
    float* jout = out + (size_t)N_BODY * NV * 3;

    k_pre<<<NJ, 256>>>(Jreg, vt, sd);
    k_jregT<<<(NV + 255) / 256, 256>>>(jreg);
    k_Bbuild<<<GN / 8, 256>>>(sd, pd);
    k_body<<<N_BODY, 32>>>(betas, thetas, trans);

    float* Cp;
    cudaGetSymbolAddress((void**)&Cp, g_C);

    cudaFuncSetAttribute(k_gemm, cudaFuncAttributeMaxDynamicSharedMemorySize, 65536);
    dim3 ggrid(GN / BN, GM / BM);
    k_gemm<<<ggrid, 256, 65536>>>(Cp);

    cudaFuncSetAttribute(k_skin, cudaFuncAttributeMaxDynamicSharedMemorySize, SKF * 4);
    dim3 sgrid(NVP / 128, N_BODY / 32);
    k_skin<<<sgrid, 128, SKF * 4>>>(vt, w, out);

    k_joints<<<N_BODY, 256>>>(out, jout);
}

// round 9
// speedup vs baseline: 3.1879x; 1.1624x over previous
#include <cuda_runtime.h>
#include <cuda_bf16.h>
#include <math.h>

#define N_BODY 512
#define NV 6890
#define NVP 6912
#define NJ 24
#define GM 512
#define GN 20736          // 3 * NVP
#define GK 256
#define NVB 108           // NVP / 64

typedef unsigned long long ull;

__device__ __constant__ int d_parents[NJ] =
    {0, 0, 0, 0, 1, 2, 3, 4, 5, 6, 7, 8, 9, 9, 9, 12, 13, 14, 16, 17, 18, 19, 20, 21};

// ---------------- scratch ----------------
__device__ float g_JT[NJ * 3];
__device__ float g_JS[NJ * 30];
__device__ __align__(16) float g_GT[NJ * 12 * N_BODY];      // [j*12+e][n]
__device__ __align__(16) float g_transT[3 * N_BODY];        // [c][n]
__device__ __align__(16) __nv_bfloat16 g_A[GM * GK];        // [n][k]
__device__ __align__(16) __nv_bfloat16 g_B[(size_t)GN * GK];// [c*NVP+v][k]
__device__ __align__(16) float g_jpart[(size_t)NVB * N_BODY * 72];

// ---------------- f32x2 helpers ----------------
__device__ __forceinline__ ull pk2(float a, float b) {
    ull r; asm("mov.b64 %0, {%1, %2};" : "=l"(r) : "f"(a), "f"(b)); return r;
}
__device__ __forceinline__ void upk2(float& a, float& b, ull v) {
    asm("mov.b64 {%0, %1}, %2;" : "=f"(a), "=f"(b) : "l"(v));
}
__device__ __forceinline__ ull fma2_(ull a, ull b, ull c) {
    ull d; asm("fma.rn.f32x2 %0, %1, %2, %3;" : "=l"(d) : "l"(a), "l"(b), "l"(c)); return d;
}

// ---------------- tensor-core helpers ----------------
__device__ __forceinline__ void cp16(unsigned dst, const void* src) {
    asm volatile("cp.async.cg.shared.global [%0], [%1], 16;" :: "r"(dst), "l"(src));
}
__device__ __forceinline__ void ldm4(unsigned* r, unsigned addr) {
    asm volatile("ldmatrix.sync.aligned.m8n8.x4.shared.b16 {%0,%1,%2,%3}, [%4];"
        : "=r"(r[0]), "=r"(r[1]), "=r"(r[2]), "=r"(r[3]) : "r"(addr));
}
__device__ __forceinline__ void mma16816(float* d, const unsigned* a, const unsigned* b) {
    asm volatile("mma.sync.aligned.m16n8k16.row.col.f32.bf16.bf16.f32 "
        "{%0,%1,%2,%3}, {%4,%5,%6,%7}, {%8,%9}, {%0,%1,%2,%3};"
        : "+f"(d[0]), "+f"(d[1]), "+f"(d[2]), "+f"(d[3])
        : "r"(a[0]), "r"(a[1]), "r"(a[2]), "r"(a[3]), "r"(b[0]), "r"(b[1]));
}
__device__ __forceinline__ int swz(int off) { return off ^ ((off >> 3) & 0x70); }

// ---------------- kernel: reduce J_regressor against template/shapedirs ----------------
__global__ void k_pre(const float* __restrict__ Jreg,
                      const float* __restrict__ vt,
                      const float* __restrict__ sd) {
    int j = blockIdx.x;
    int tid = threadIdx.x;
    float acc[33];
#pragma unroll
    for (int i = 0; i < 33; i++) acc[i] = 0.f;
    for (int v = tid; v < NV; v += 256) {
        float r = Jreg[j * NV + v];
#pragma unroll
        for (int c = 0; c < 3; c++) acc[c] += r * vt[v * 3 + c];
#pragma unroll
        for (int i = 0; i < 30; i++) acc[3 + i] += r * sd[v * 30 + i];
    }
#pragma unroll
    for (int i = 0; i < 33; i++) {
#pragma unroll
        for (int off = 16; off > 0; off >>= 1)
            acc[i] += __shfl_down_sync(0xffffffff, acc[i], off);
    }
    __shared__ float red[8][34];
    int wid = tid >> 5, lane = tid & 31;
    if (lane == 0) {
#pragma unroll
        for (int i = 0; i < 33; i++) red[wid][i] = acc[i];
    }
    __syncthreads();
    if (tid < 33) {
        float s = 0.f;
#pragma unroll
        for (int wq = 0; wq < 8; wq++) s += red[wq][tid];
        if (tid < 3) g_JT[j * 3 + tid] = s;
        else         g_JS[j * 30 + (tid - 3)] = s;
    }
}

// ---------------- kernel: build bf16 B [c*NVP+v][k] ----------------
// k 0-9: shapedirs; 10-216: posedirs; 217: bf16(vt) (hi); 218: vt - hi (lo); rest 0
__global__ void __launch_bounds__(256) k_Bbuild(const float* __restrict__ sd,
                                                const float* __restrict__ pd,
                                                const float* __restrict__ vt) {
    int wid = threadIdx.x >> 5, lane = threadIdx.x & 31;
    int row = blockIdx.x * 8 + wid;
    int c = row / NVP, v = row % NVP;
#pragma unroll
    for (int t = 0; t < 8; t++) {
        int k = t * 32 + lane;
        float val = 0.f;
        if (v < NV) {
            if (k < 10)        val = sd[v * 30 + c * 10 + k];
            else if (k < 217)  val = pd[(size_t)v * 621 + c * 207 + (k - 10)];
            else if (k == 217) val = vt[v * 3 + c];
            else if (k == 218) {
                float x = vt[v * 3 + c];
                val = x - __bfloat162float(__float2bfloat16(x));
            }
        }
        g_B[(size_t)row * GK + k] = __float2bfloat16(val);
    }
}

// ---------------- kernel: rodrigues + FK + A row (4 bodies/block, 1 warp each) ----------------
__global__ void __launch_bounds__(128) k_body(const float* __restrict__ betas,
                                              const float* __restrict__ thetas,
                                              const float* __restrict__ trans) {
    int wb = threadIdx.x >> 5;
    int lane = threadIdx.x & 31;
    int n = blockIdx.x * 4 + wb;
    __shared__ float sR[4][NJ][9];
    __shared__ float sJ[4][NJ][3];
    __shared__ float sT[4][NJ][3];
    __shared__ float sG[4][NJ][12];

    if (lane < NJ) {
        int j = lane;
        float b[10];
#pragma unroll
        for (int k = 0; k < 10; k++) b[k] = betas[n * 10 + k];
#pragma unroll
        for (int c = 0; c < 3; c++) {
            float a = g_JT[j * 3 + c];
#pragma unroll
            for (int k = 0; k < 10; k++) a += g_JS[j * 30 + c * 10 + k] * b[k];
            sJ[wb][j][c] = a;
        }
        float rx = thetas[n * 72 + j * 3 + 0];
        float ry = thetas[n * 72 + j * 3 + 1];
        float rz = thetas[n * 72 + j * 3 + 2];
        float th = sqrtf(rx * rx + ry * ry + rz * rz) + 1e-8f;
        float inv = 1.0f / th;
        float x = rx * inv, y = ry * inv, z = rz * inv;
        float ct = cosf(th), st = sinf(th), oc = 1.0f - ct;
        sR[wb][j][0] = ct + oc * x * x;      sR[wb][j][1] = oc * x * y - st * z;  sR[wb][j][2] = oc * x * z + st * y;
        sR[wb][j][3] = oc * y * x + st * z;  sR[wb][j][4] = ct + oc * y * y;      sR[wb][j][5] = oc * y * z - st * x;
        sR[wb][j][6] = oc * z * x - st * y;  sR[wb][j][7] = oc * z * y + st * x;  sR[wb][j][8] = ct + oc * z * z;
    }
    __syncwarp();
    if (lane < NJ) {
        int j = lane;
        if (j == 0) {
#pragma unroll
            for (int c = 0; c < 3; c++) sT[wb][0][c] = sJ[wb][0][c];
        } else {
            int p = d_parents[j];
#pragma unroll
            for (int c = 0; c < 3; c++) sT[wb][j][c] = sJ[wb][j][c] - sJ[wb][p][c];
        }
    }
    __syncwarp();
    if (lane == 0) {
#pragma unroll
        for (int r = 0; r < 3; r++) {
            sG[wb][0][r * 4 + 0] = sR[wb][0][r * 3 + 0];
            sG[wb][0][r * 4 + 1] = sR[wb][0][r * 3 + 1];
            sG[wb][0][r * 4 + 2] = sR[wb][0][r * 3 + 2];
            sG[wb][0][r * 4 + 3] = sT[wb][0][r];
        }
        for (int j = 1; j < NJ; j++) {
            int p = d_parents[j];
            float Rn[9], tn[3];
#pragma unroll
            for (int r = 0; r < 3; r++) {
#pragma unroll
                for (int c = 0; c < 3; c++) {
                    Rn[r * 3 + c] = sG[wb][p][r * 4 + 0] * sR[wb][j][0 * 3 + c]
                                  + sG[wb][p][r * 4 + 1] * sR[wb][j][1 * 3 + c]
                                  + sG[wb][p][r * 4 + 2] * sR[wb][j][2 * 3 + c];
                }
                tn[r] = sG[wb][p][r * 4 + 3]
                      + sG[wb][p][r * 4 + 0] * sT[wb][j][0]
                      + sG[wb][p][r * 4 + 1] * sT[wb][j][1]
                      + sG[wb][p][r * 4 + 2] * sT[wb][j][2];
            }
#pragma unroll
            for (int r = 0; r < 3; r++) {
                sG[wb][j][r * 4 + 0] = Rn[r * 3 + 0];
                sG[wb][j][r * 4 + 1] = Rn[r * 3 + 1];
                sG[wb][j][r * 4 + 2] = Rn[r * 3 + 2];
                sG[wb][j][r * 4 + 3] = tn[r];
            }
        }
    }
    __syncwarp();
    if (lane < NJ) {
        int j = lane;
        float t0 = sG[wb][j][3]  - (sG[wb][j][0] * sJ[wb][j][0] + sG[wb][j][1] * sJ[wb][j][1] + sG[wb][j][2]  * sJ[wb][j][2]);
        float t1 = sG[wb][j][7]  - (sG[wb][j][4] * sJ[wb][j][0] + sG[wb][j][5] * sJ[wb][j][1] + sG[wb][j][6]  * sJ[wb][j][2]);
        float t2 = sG[wb][j][11] - (sG[wb][j][8] * sJ[wb][j][0] + sG[wb][j][9] * sJ[wb][j][1] + sG[wb][j][10] * sJ[wb][j][2]);
        sG[wb][j][3] = t0; sG[wb][j][7] = t1; sG[wb][j][11] = t2;
    }
    __syncwarp();
    for (int idx = lane; idx < NJ * 12; idx += 32)
        g_GT[idx * N_BODY + n] = sG[wb][idx / 12][idx % 12];
    // A row: [betas(10) | lrotmin(207) | 1 | 1 | zeros]
#pragma unroll
    for (int t = 0; t < 8; t++) {
        int k = t * 32 + lane;
        float val = 0.f;
        if (k < 10) val = betas[n * 10 + k];
        else if (k < 217) {
            int idx = k - 10;
            int j = idx / 9 + 1, e = idx % 9;
            val = sR[wb][j][e];
            if (e == 0 || e == 4 || e == 8) val -= 1.0f;
        }
        else if (k == 217 || k == 218) val = 1.0f;
        g_A[n * GK + k] = __float2bfloat16(val);
    }
    if (lane < 3) g_transT[lane * N_BODY + n] = trans[n * 3 + lane];
}

// ---------------- fused kernel: GEMM (v_posed) + LBS + joint partials ----------------
// block: 128 bodies x 64 verts, 256 threads, 8 warps (2 M x 4 N), warp tile 64x16 per c
// smem floats: Ct[128][196] @0 (25088) | w_s[24][128] @25088 | jreg_s[24][64] @28160
//              | sG[288][64] @29696 -> total 48128 floats = 192512 B
// cp.async stages (bytes): A 2x16KB @0, B 2x(3x8KB) @32768 -> 80KB (overlaps Ct, temporal)
#define CTS 196
#define SMEMB 192512

__global__ void __launch_bounds__(256) k_fused(const float* __restrict__ w,
                                               const float* __restrict__ jreg,
                                               float* __restrict__ out) {
    extern __shared__ float sm[];
    unsigned smem = (unsigned)__cvta_generic_to_shared((char*)sm);
    float* Ct     = sm;
    float* w_s    = sm + 25088;
    float* jreg_s = sm + 28160;
    float* sG     = sm + 29696;

    int tid = threadIdx.x, lane = tid & 31, wid = tid >> 5;
    int warp_m = (wid >> 2) * 64, warp_n = (wid & 3) * 16;
    int vbIdx = blockIdx.x;
    int vb = vbIdx * 64;
    int mb = blockIdx.y * 128;

    // stage w (pair-duplicated) + jreg tile (zero-padded)
    for (int i = tid; i < 64 * 24; i += 256) {
        int vl = i / 24, j = i % 24;
        int v = vb + vl;
        float wv = (v < NV) ? w[v * 24 + j] : 0.f;
        w_s[j * 128 + vl * 2]     = wv;
        w_s[j * 128 + vl * 2 + 1] = wv;
        jreg_s[j * 64 + vl] = (v < NV) ? jreg[v * 24 + j] : 0.f;
    }

    float acc[3][4][2][4];
#pragma unroll
    for (int c = 0; c < 3; c++)
#pragma unroll
        for (int mf = 0; mf < 4; mf++)
#pragma unroll
            for (int nf = 0; nf < 2; nf++)
#pragma unroll
                for (int q = 0; q < 4; q++) acc[c][mf][nf][q] = 0.f;

#define LDSTG(st, kb)                                                              \
    {                                                                              \
        unsigned sa = smem + (st) * 16384;                                         \
        _Pragma("unroll")                                                          \
        for (int t = 0; t < 4; t++) {                                              \
            int i = tid + t * 256; int r = i >> 3, u = i & 7;                      \
            cp16(sa + swz(r * 128 + u * 16),                                       \
                 (const char*)g_A + (size_t)(mb + r) * 512 + (kb) * 128 + u * 16); \
        }                                                                          \
        _Pragma("unroll")                                                          \
        for (int t = 0; t < 6; t++) {                                              \
            int i = tid + t * 256; int c = i >> 9, rr = (i >> 3) & 63, u = i & 7;  \
            unsigned sb = smem + 32768 + (st) * 24576 + c * 8192;                  \
            cp16(sb + swz(rr * 128 + u * 16),                                      \
                 (const char*)g_B + (size_t)(c * NVP + vb + rr) * 512 + (kb) * 128 + u * 16); \
        }                                                                          \
        asm volatile("cp.async.commit_group;");                                    \
    }

    LDSTG(0, 0);
#pragma unroll
    for (int kb = 0; kb < 4; kb++) {
        if (kb < 3) LDSTG((kb + 1) & 1, kb + 1);
        if (kb < 3) asm volatile("cp.async.wait_group 1;");
        else        asm volatile("cp.async.wait_group 0;");
        __syncthreads();
        unsigned sa = smem + (kb & 1) * 16384;
#pragma unroll
        for (int s = 0; s < 4; s++) {
            unsigned af[4][4];
#pragma unroll
            for (int mf = 0; mf < 4; mf++) {
                int row = warp_m + mf * 16 + (lane & 7) + ((lane >> 3) & 1) * 8;
                ldm4(af[mf], sa + swz(row * 128 + s * 32 + ((lane >> 4) & 1) * 16));
            }
#pragma unroll
            for (int c = 0; c < 3; c++) {
                unsigned sb = smem + 32768 + (kb & 1) * 24576 + c * 8192;
                unsigned r[4];
                int row = warp_n + (lane & 7) + ((lane >> 4) & 1) * 8;
                ldm4(r, sb + swz(row * 128 + s * 32 + ((lane >> 3) & 1) * 16));
#pragma unroll
                for (int mf = 0; mf < 4; mf++) {
                    mma16816(acc[c][mf][0], af[mf], r);
                    mma16816(acc[c][mf][1], af[mf], r + 2);
                }
            }
        }
        __syncthreads();
    }
#undef LDSTG

    // ---- epilogue: acc -> Ct (v_posed, vt already folded in via hi/lo columns) ----
#pragma unroll
    for (int c = 0; c < 3; c++)
#pragma unroll
        for (int mf = 0; mf < 4; mf++)
#pragma unroll
            for (int nf = 0; nf < 2; nf++) {
                int r0 = warp_m + mf * 16 + (lane >> 2);
                int L = warp_n + nf * 8 + (lane & 3) * 2;
                Ct[r0 * CTS + L * 3 + c]           = acc[c][mf][nf][0];
                Ct[r0 * CTS + (L + 1) * 3 + c]     = acc[c][mf][nf][1];
                Ct[(r0 + 8) * CTS + L * 3 + c]     = acc[c][mf][nf][2];
                Ct[(r0 + 8) * CTS + (L + 1) * 3 + c] = acc[c][mf][nf][3];
            }
    __syncthreads();

    // ---- skinning, in place, two 64-body halves ----
    int bp = tid >> 3, vq = tid & 7;
#pragma unroll 1
    for (int h = 0; h < 2; h++) {
        if (h) __syncthreads();
        for (int i = tid; i < 288 * 64; i += 256)
            sG[i] = g_GT[(i >> 6) * N_BODY + mb + h * 64 + (i & 63)];
        __syncthreads();

        int n0 = h * 64 + bp * 2;
        ull B[8][3], o[8][3];
#pragma unroll
        for (int vv = 0; vv < 8; vv++)
#pragma unroll
            for (int c = 0; c < 3; c++)
                B[vv][c] = pk2(Ct[n0 * CTS + (vq * 8 + vv) * 3 + c],
                               Ct[(n0 + 1) * CTS + (vq * 8 + vv) * 3 + c]);
#pragma unroll
        for (int c = 0; c < 3; c++) {
            ull t2 = *(const ull*)(g_transT + c * N_BODY + mb + n0);
#pragma unroll
            for (int vv = 0; vv < 8; vv++) o[vv][c] = t2;
        }
#pragma unroll 1
        for (int j = 0; j < NJ; j++) {
            ull g2[12];
#pragma unroll
            for (int e = 0; e < 12; e++)
                g2[e] = *(const ull*)(sG + (j * 12 + e) * 64 + bp * 2);
#pragma unroll
            for (int vv = 0; vv < 8; vv++) {
                ull w2 = *(const ull*)(w_s + j * 128 + (vq * 8 + vv) * 2);
                ull tx = fma2_(g2[0], B[vv][0], fma2_(g2[1], B[vv][1], fma2_(g2[2],  B[vv][2], g2[3])));
                ull ty = fma2_(g2[4], B[vv][0], fma2_(g2[5], B[vv][1], fma2_(g2[6],  B[vv][2], g2[7])));
                ull tz = fma2_(g2[8], B[vv][0], fma2_(g2[9], B[vv][1], fma2_(g2[10], B[vv][2], g2[11])));
                o[vv][0] = fma2_(w2, tx, o[vv][0]);
                o[vv][1] = fma2_(w2, ty, o[vv][1]);
                o[vv][2] = fma2_(w2, tz, o[vv][2]);
            }
        }
#pragma unroll
        for (int vv = 0; vv < 8; vv++)
#pragma unroll
            for (int c = 0; c < 3; c++) {
                float x0, x1;
                upk2(x0, x1, o[vv][c]);
                Ct[n0 * CTS + (vq * 8 + vv) * 3 + c]       = x0;
                Ct[(n0 + 1) * CTS + (vq * 8 + vv) * 3 + c] = x1;
            }
    }
    __syncthreads();

    // ---- stream out (float2 coalesced) ----
    int nvleft = NV - vb; if (nvleft > 64) nvleft = 64;
    int flim2 = nvleft * 3 / 2;
    for (int i = tid; i < 128 * 96; i += 256) {
        int nl = i / 96, q = i % 96;
        if (q < flim2)
            *(float2*)(out + (size_t)(mb + nl) * (NV * 3) + (size_t)vb * 3 + 2 * q) =
                *(const float2*)(Ct + nl * CTS + 2 * q);
    }

    // ---- joint partials: thread = (body, half-of-joints) ----
    {
        int nl = tid >> 1, jh = (tid & 1) * 12;
        float ja[36];
#pragma unroll
        for (int q = 0; q < 36; q++) ja[q] = 0.f;
#pragma unroll 4
        for (int v = 0; v < 64; v++) {
            float r0 = Ct[nl * CTS + v * 3 + 0];
            float r1 = Ct[nl * CTS + v * 3 + 1];
            float r2 = Ct[nl * CTS + v * 3 + 2];
#pragma unroll
            for (int j = 0; j < 12; j++) {
                float jr = jreg_s[(jh + j) * 64 + v];
                ja[j * 3 + 0] += jr * r0;
                ja[j * 3 + 1] += jr * r1;
                ja[j * 3 + 2] += jr * r2;
            }
        }
        float* dst = g_jpart + (size_t)vbIdx * (N_BODY * 72) + (mb + nl) * 72 + jh * 3;
#pragma unroll
        for (int q = 0; q < 36; q++) dst[q] = ja[q];
    }
}

// ---------------- kernel: reduce joint partials ----------------
__global__ void __launch_bounds__(256) k_jred(float* __restrict__ jout) {
    int i = blockIdx.x * 256 + threadIdx.x;
    if (i < N_BODY * 72) {
        float s = 0.f;
        for (int b = 0; b < NVB; b++) s += g_jpart[(size_t)b * (N_BODY * 72) + i];
        jout[i] = s;
    }
}

// ---------------- launch ----------------
extern "C" void kernel_launch(void* const* d_in, const int* in_sizes, int n_in,
                              void* d_out, int out_size) {
    const float* betas  = (const float*)d_in[0];
    const float* thetas = (const float*)d_in[1];
    const float* trans  = (const float*)d_in[2];
    const float* vt     = (const float*)d_in[3];
    const float* sd     = (const float*)d_in[4];
    const float* pd     = (const float*)d_in[5];
    const float* Jreg   = (const float*)d_in[6];
    const float* jreg   = (const float*)d_in[7];
    const float* w      = (const float*)d_in[8];
    float* out  = (float*)d_out;
    float* jout = out + (size_t)N_BODY * NV * 3;

    k_pre<<<NJ, 256>>>(Jreg, vt, sd);
    k_Bbuild<<<GN / 8, 256>>>(sd, pd, vt);
    k_body<<<N_BODY / 4, 128>>>(betas, thetas, trans);

    cudaFuncSetAttribute(k_fused, cudaFuncAttributeMaxDynamicSharedMemorySize, SMEMB);
    dim3 fgrid(NVB, N_BODY / 128);
    k_fused<<<fgrid, 256, SMEMB>>>(w, jreg, out);

    k_jred<<<(N_BODY * 72 + 255) / 256, 256>>>(jout);
}